// round 1
// baseline (speedup 1.0000x reference)
#include <cuda_runtime.h>
#include <math.h>

#define N_NODES 50000
#define N_EDGES 100000
#define FN 22
#define FE 4
#define H 64
#define BN_EPS 1e-5

// ---------------- scratch (static device globals; no allocation) ----------------
__device__ float  d_agg1[N_NODES * H];   // layer1 pre-BN accumulator
__device__ float  d_h1  [N_NODES * H];   // layer1 post-BN-ReLU
__device__ float  d_agg2[N_NODES * H];   // layer2 pre-BN accumulator
__device__ float4 d_We1t[FN * H];        // transposed We1: [j].{x,y,z,w} = We1[f=0..3][j]
__device__ float4 d_We2t[H * H];         // transposed We2
__device__ double d_stats[4 * H];        // sum1, sumsq1, sum2, sumsq2
__device__ float  d_scale[2 * H];
__device__ float  d_shift[2 * H];

// ---------------- prep: transpose edge-MLP weights, zero stats ----------------
__global__ void k_prep(const float* __restrict__ We1, const float* __restrict__ We2) {
    int j = blockIdx.x * blockDim.x + threadIdx.x;
    if (j < FN * H)
        d_We1t[j] = make_float4(We1[j], We1[FN*H + j], We1[2*FN*H + j], We1[3*FN*H + j]);
    if (j < H * H)
        d_We2t[j] = make_float4(We2[j], We2[H*H + j], We2[2*H*H + j], We2[3*H*H + j]);
    if (j < 4 * H) d_stats[j] = 0.0;
}

// ---------------- agg1 = x @ root1 + b1 ----------------
__global__ void k_init_agg1(const float* __restrict__ x,
                            const float* __restrict__ root1,
                            const float* __restrict__ b1) {
    __shared__ float sr[FN * H];
    for (int t = threadIdx.x; t < FN * H; t += blockDim.x) sr[t] = root1[t];
    __syncthreads();
    int idx = blockIdx.x * blockDim.x + threadIdx.x;
    if (idx >= N_NODES * H) return;
    int n = idx >> 6, o = idx & 63;
    float acc = __ldg(&b1[o]);
#pragma unroll
    for (int f = 0; f < FN; f++)
        acc = fmaf(__ldg(&x[n * FN + f]), sr[f * H + o], acc);
    d_agg1[idx] = acc;
}

// ---------------- layer-1 edge kernel ----------------
// 256 threads: o = tid&63 (output col), ig = tid>>6 (i-group of 6; 4*6=24 >= 22).
// Edge-MLP weights register-resident; x[src] staged in shared.
__global__ __launch_bounds__(256, 2)
void k_edge1(const float* __restrict__ x, const float* __restrict__ ea,
             const float* __restrict__ be1, const int* __restrict__ eidx) {
    const int o  = threadIdx.x & 63;
    const int ig = threadIdx.x >> 6;
    float4 W[6]; float B[6];
#pragma unroll
    for (int ii = 0; ii < 6; ii++) {
        int i = ig * 6 + ii;
        if (i < FN) { W[ii] = d_We1t[i * H + o]; B[ii] = __ldg(&be1[i * H + o]); }
        else        { W[ii] = make_float4(0.f, 0.f, 0.f, 0.f); B[ii] = 0.f; }
    }
    __shared__ float sh_x[24];
    __shared__ float sh_part[256];
    if (threadIdx.x >= FN && threadIdx.x < 24) sh_x[threadIdx.x] = 0.f;

    for (int e = blockIdx.x; e < N_EDGES; e += gridDim.x) {
        int src = __ldg(&eidx[e]);
        int dst = __ldg(&eidx[N_EDGES + e]);
        if (threadIdx.x < FN) sh_x[threadIdx.x] = __ldg(&x[src * FN + threadIdx.x]);
        __syncthreads();
        float4 a = __ldg(&((const float4*)ea)[e]);
        float acc = 0.f;
#pragma unroll
        for (int ii = 0; ii < 6; ii++) {
            float w = fmaf(a.x, W[ii].x, B[ii]);
            w = fmaf(a.y, W[ii].y, w);
            w = fmaf(a.z, W[ii].z, w);
            w = fmaf(a.w, W[ii].w, w);
            w = fmaxf(w, 0.f);
            acc = fmaf(sh_x[ig * 6 + ii], w, acc);
        }
        sh_part[threadIdx.x] = acc;
        __syncthreads();
        if (threadIdx.x < H) {
            float m = sh_part[threadIdx.x] + sh_part[threadIdx.x + 64]
                    + sh_part[threadIdx.x + 128] + sh_part[threadIdx.x + 192];
            atomicAdd(&d_agg1[dst * H + threadIdx.x], m);
        }
        // no extra barrier needed: next-iter shared writes are by tid<64 only,
        // and all readers have passed the second barrier.
    }
}

// ---------------- BN stats (double accumulation) ----------------
__global__ void k_stats(int layer) {
    const float* __restrict__ src = layer ? d_agg2 : d_agg1;
    int o = threadIdx.x & 63;
    int r = threadIdx.x >> 6;
    double s = 0.0, ss = 0.0;
    for (int n = blockIdx.x * 4 + r; n < N_NODES; n += gridDim.x * 4) {
        double v = (double)src[n * H + o];
        s += v; ss += v * v;
    }
    __shared__ double sh_s[256], sh_ss[256];
    sh_s[threadIdx.x] = s; sh_ss[threadIdx.x] = ss;
    __syncthreads();
    if (threadIdx.x < H) {
        s  = sh_s[threadIdx.x]  + sh_s[threadIdx.x + 64]  + sh_s[threadIdx.x + 128]  + sh_s[threadIdx.x + 192];
        ss = sh_ss[threadIdx.x] + sh_ss[threadIdx.x + 64] + sh_ss[threadIdx.x + 128] + sh_ss[threadIdx.x + 192];
        atomicAdd(&d_stats[layer * 2 * H + o], s);
        atomicAdd(&d_stats[layer * 2 * H + H + o], ss);
    }
}

// ---------------- BN finalize: fold into scale/shift ----------------
__global__ void k_finalize(int layer, const float* __restrict__ g,
                           const float* __restrict__ beta) {
    int o = threadIdx.x;
    if (o >= H) return;
    double s  = d_stats[layer * 2 * H + o];
    double ss = d_stats[layer * 2 * H + H + o];
    double mu  = s / (double)N_NODES;
    double var = ss / (double)N_NODES - mu * mu;
    float rs = (float)(1.0 / sqrt(var + BN_EPS));
    float sc = __ldg(&g[o]) * rs;
    d_scale[layer * H + o] = sc;
    d_shift[layer * H + o] = __ldg(&beta[o]) - (float)mu * sc;
}

// ---------------- BN1 apply + ReLU -> h1 ----------------
__global__ void k_apply1() {
    int idx = blockIdx.x * blockDim.x + threadIdx.x;
    if (idx >= N_NODES * H) return;
    int o = idx & 63;
    d_h1[idx] = fmaxf(fmaf(d_agg1[idx], d_scale[o], d_shift[o]), 0.f);
}

// ---------------- agg2 = h1 @ root2 + b2 ----------------
__global__ void k_init_agg2(const float* __restrict__ root2,
                            const float* __restrict__ b2) {
    __shared__ float sr[H * H];
    for (int t = threadIdx.x; t < H * H; t += blockDim.x) sr[t] = root2[t];
    __syncthreads();
    int idx = blockIdx.x * blockDim.x + threadIdx.x;
    if (idx >= N_NODES * H) return;
    int n = idx >> 6, o = idx & 63;
    const float4* hrow = (const float4*)(d_h1 + n * H);
    float acc = __ldg(&b2[o]);
#pragma unroll
    for (int q = 0; q < 16; q++) {
        float4 hv = hrow[q];
        acc = fmaf(hv.x, sr[(4 * q + 0) * H + o], acc);
        acc = fmaf(hv.y, sr[(4 * q + 1) * H + o], acc);
        acc = fmaf(hv.z, sr[(4 * q + 2) * H + o], acc);
        acc = fmaf(hv.w, sr[(4 * q + 3) * H + o], acc);
    }
    d_agg2[idx] = acc;
}

// ---------------- layer-2 edge kernel (dominant) ----------------
// 256 threads: o = tid&63, ig = tid>>6 covers i in [ig*16, ig*16+16).
// 80 regs of We2/be2 per thread, held across all edges of the block.
__global__ __launch_bounds__(256, 2)
void k_edge2(const float* __restrict__ ea, const float* __restrict__ be2,
             const int* __restrict__ eidx) {
    const int o  = threadIdx.x & 63;
    const int ig = threadIdx.x >> 6;
    float4 W[16]; float B[16];
#pragma unroll
    for (int ii = 0; ii < 16; ii++) {
        int i = ig * 16 + ii;
        W[ii] = d_We2t[i * H + o];
        B[ii] = __ldg(&be2[i * H + o]);
    }
    __shared__ float sh_h[H];
    __shared__ float sh_part[256];

    for (int e = blockIdx.x; e < N_EDGES; e += gridDim.x) {
        int src = __ldg(&eidx[e]);
        int dst = __ldg(&eidx[N_EDGES + e]);
        if (threadIdx.x < H) sh_h[threadIdx.x] = d_h1[src * H + threadIdx.x];
        __syncthreads();
        float4 a = __ldg(&((const float4*)ea)[e]);
        float acc = 0.f;
#pragma unroll
        for (int ii = 0; ii < 16; ii++) {
            float w = fmaf(a.x, W[ii].x, B[ii]);
            w = fmaf(a.y, W[ii].y, w);
            w = fmaf(a.z, W[ii].z, w);
            w = fmaf(a.w, W[ii].w, w);
            w = fmaxf(w, 0.f);
            acc = fmaf(sh_h[ig * 16 + ii], w, acc);
        }
        sh_part[threadIdx.x] = acc;
        __syncthreads();
        if (threadIdx.x < H) {
            float m = sh_part[threadIdx.x] + sh_part[threadIdx.x + 64]
                    + sh_part[threadIdx.x + 128] + sh_part[threadIdx.x + 192];
            atomicAdd(&d_agg2[dst * H + threadIdx.x], m);
        }
    }
}

// ---------------- BN2 apply + ReLU + FC + sigmoid ----------------
__global__ void k_final(const float* __restrict__ Wfc, const float* __restrict__ bfc,
                        float* __restrict__ out) {
    __shared__ float sh_w[8];
    int idx = blockIdx.x * blockDim.x + threadIdx.x;
    int n = idx >> 6, o = idx & 63;
    float p = 0.f;
    if (n < N_NODES) {
        float v = fmaxf(fmaf(d_agg2[idx], d_scale[H + o], d_shift[H + o]), 0.f);
        p = v * __ldg(&Wfc[o]);
    }
#pragma unroll
    for (int off = 16; off > 0; off >>= 1)
        p += __shfl_down_sync(0xffffffffu, p, off);
    if ((threadIdx.x & 31) == 0) sh_w[threadIdx.x >> 5] = p;
    __syncthreads();
    if (threadIdx.x < 4) {
        int nn = blockIdx.x * 4 + threadIdx.x;
        if (nn < N_NODES) {
            float t = sh_w[2 * threadIdx.x] + sh_w[2 * threadIdx.x + 1] + __ldg(bfc);
            out[nn] = 1.f / (1.f + expf(-t));
        }
    }
}

// ---------------- launch ----------------
extern "C" void kernel_launch(void* const* d_in, const int* in_sizes, int n_in,
                              void* d_out, int out_size) {
    const float* x     = (const float*)d_in[0];
    const float* ea    = (const float*)d_in[1];
    const float* We1   = (const float*)d_in[2];
    const float* be1   = (const float*)d_in[3];
    const float* root1 = (const float*)d_in[4];
    const float* b1    = (const float*)d_in[5];
    const float* g1    = (const float*)d_in[6];
    const float* beta1 = (const float*)d_in[7];
    const float* We2   = (const float*)d_in[8];
    const float* be2   = (const float*)d_in[9];
    const float* root2 = (const float*)d_in[10];
    const float* b2    = (const float*)d_in[11];
    const float* g2    = (const float*)d_in[12];
    const float* beta2 = (const float*)d_in[13];
    const float* Wfc   = (const float*)d_in[14];
    const float* bfc   = (const float*)d_in[15];
    const int*   eidx  = (const int*)d_in[16];
    float* out = (float*)d_out;

    const int NB_ELEM = (N_NODES * H + 255) / 256;   // 12500

    k_prep<<<16, 256>>>(We1, We2);
    k_init_agg1<<<NB_ELEM, 256>>>(x, root1, b1);
    k_edge1<<<296, 256>>>(x, ea, be1, eidx);
    k_stats<<<256, 256>>>(0);
    k_finalize<<<1, 64>>>(0, g1, beta1);
    k_apply1<<<NB_ELEM, 256>>>();
    k_init_agg2<<<NB_ELEM, 256>>>(root2, b2);
    k_edge2<<<296, 256>>>(ea, be2, eidx);
    k_stats<<<256, 256>>>(1);
    k_finalize<<<1, 64>>>(1, g2, beta2);
    k_final<<<NB_ELEM, 256>>>(Wfc, bfc, out);
}

// round 4
// speedup vs baseline: 1.6255x; 1.6255x over previous
#include <cuda_runtime.h>
#include <math.h>

#define N_NODES 50000
#define N_EDGES 100000
#define FN 22
#define FE 4
#define H 64
#define BN_EPS 1e-5
#define EB 8            // edges per block-batch

typedef unsigned long long u64;

// ---------------- packed f32x2 helpers ----------------
__device__ __forceinline__ u64 pack2(float lo, float hi) {
    u64 r; asm("mov.b64 %0, {%1, %2};" : "=l"(r) : "f"(lo), "f"(hi)); return r;
}
__device__ __forceinline__ void unpack2(u64 v, float& lo, float& hi) {
    asm("mov.b64 {%0, %1}, %2;" : "=f"(lo), "=f"(hi) : "l"(v));
}
__device__ __forceinline__ u64 fma2(u64 a, u64 b, u64 c) {
    u64 d; asm("fma.rn.f32x2 %0, %1, %2, %3;" : "=l"(d) : "l"(a), "l"(b), "l"(c)); return d;
}
__device__ __forceinline__ u64 relu2(u64 v) {
    float a, b; unpack2(v, a, b);
    return pack2(fmaxf(a, 0.f), fmaxf(b, 0.f));
}

// ---------------- scratch (static device globals) ----------------
__device__ float d_agg1[N_NODES * H];
__device__ float d_h1  [N_NODES * H];
__device__ float d_agg2[N_NODES * H];
__device__ u64   d_We1p[24 * 32 * 4];   // [i<24][cp<32][f<4] packed col-pairs (zero-padded i>=22)
__device__ u64   d_be1p[24 * 32];
__device__ u64   d_We2p[64 * 32 * 4];
__device__ u64   d_be2p[64 * 32];
__device__ u64   d_root2p[64 * 32];     // [i][cp]
__device__ float d_stats[4 * H];        // sum1, sq1, sum2, sq2
__device__ float d_scale[2 * H];
__device__ float d_shift[2 * H];

// ---------------- prep: pack weights, zero stats ----------------
__global__ void k_prep(const float* __restrict__ We1, const float* __restrict__ be1,
                       const float* __restrict__ We2, const float* __restrict__ be2,
                       const float* __restrict__ root2) {
    int j = blockIdx.x * blockDim.x + threadIdx.x;
    if (j < 64 * 32 * 4) {
        int f = j & 3, cp = (j >> 2) & 31, i = j >> 7;
        d_We2p[j] = pack2(We2[f * 4096 + i * 64 + 2 * cp], We2[f * 4096 + i * 64 + 2 * cp + 1]);
    }
    if (j < 24 * 32 * 4) {
        int f = j & 3, cp = (j >> 2) & 31, i = j >> 7;
        d_We1p[j] = (i < FN) ? pack2(We1[f * 1408 + i * 64 + 2 * cp],
                                     We1[f * 1408 + i * 64 + 2 * cp + 1]) : 0ULL;
    }
    if (j < 64 * 32) {
        int cp = j & 31, i = j >> 5;
        d_be2p[j]   = pack2(be2[i * 64 + 2 * cp],   be2[i * 64 + 2 * cp + 1]);
        d_root2p[j] = pack2(root2[i * 64 + 2 * cp], root2[i * 64 + 2 * cp + 1]);
    }
    if (j < 24 * 32) {
        int cp = j & 31, i = j >> 5;
        d_be1p[j] = (i < FN) ? pack2(be1[i * 64 + 2 * cp], be1[i * 64 + 2 * cp + 1]) : 0ULL;
    }
    if (j < 4 * H) d_stats[j] = 0.f;
}

// ---------------- agg1 = x @ root1 + b1 ----------------
__global__ void k_init_agg1(const float* __restrict__ x,
                            const float* __restrict__ root1,
                            const float* __restrict__ b1) {
    __shared__ float sr[FN * H];
    for (int t = threadIdx.x; t < FN * H; t += blockDim.x) sr[t] = root1[t];
    __syncthreads();
    int idx = blockIdx.x * blockDim.x + threadIdx.x;
    if (idx >= N_NODES * H) return;
    int n = idx >> 6, o = idx & 63;
    float acc = __ldg(&b1[o]);
#pragma unroll
    for (int f = 0; f < FN; f++)
        acc = fmaf(__ldg(&x[n * FN + f]), sr[f * H + o], acc);
    d_agg1[idx] = acc;
}

// ---------------- layer-1 edge kernel ----------------
// thread: cp = tid>>3 (column pair 0..31), ig = tid&7 (i-group of 3, covers 24 padded inputs)
__global__ __launch_bounds__(256, 2)
void k_edge1(const float* __restrict__ x, const float4* __restrict__ ea4,
             const int* __restrict__ eidx) {
    const int tid = threadIdx.x;
    const int cp = tid >> 3;
    const int ig = tid & 7;
    const int wid = tid >> 5, lane = tid & 31;
    u64 W[3][4]; u64 B[3];
#pragma unroll
    for (int ii = 0; ii < 3; ii++) {
        int i = ig * 3 + ii;
#pragma unroll
        for (int f = 0; f < 4; f++) W[ii][f] = d_We1p[(i * 32 + cp) * 4 + f];
        B[ii] = d_be1p[i * 32 + cp];
    }
    __shared__ float  sh_x[2][EB][24];
    __shared__ float4 sh_ea[2][EB];
    __shared__ int    sh_dst[2][EB];

    auto load = [&](int b, int buf) {
        int e = b + wid;                 // warp wid loads edge wid of batch
        if (e < N_EDGES) {
            int src = __ldg(&eidx[e]);
            if (lane < 24)
                sh_x[buf][wid][lane] = (lane < FN) ? __ldg(&x[src * FN + lane]) : 0.f;
            if (lane == 0) {
                sh_ea[buf][wid]  = __ldg(&ea4[e]);
                sh_dst[buf][wid] = __ldg(&eidx[N_EDGES + e]);
            }
        }
    };

    const int step = gridDim.x * EB;
    int base = blockIdx.x * EB;
    load(base, 0);
    int buf = 0;
    for (int b = base; b < N_EDGES; b += step) {
        __syncthreads();
        if (b + step < N_EDGES) load(b + step, buf ^ 1);
        int emax = min(EB, N_EDGES - b);
        for (int k = 0; k < emax; k++) {
            float4 a = sh_ea[buf][k];
            u64 ax = pack2(a.x, a.x), ay = pack2(a.y, a.y);
            u64 az = pack2(a.z, a.z), aw = pack2(a.w, a.w);
            u64 acc = 0ULL;
#pragma unroll
            for (int ii = 0; ii < 3; ii++) {
                u64 w = fma2(ax, W[ii][0], B[ii]);
                w = fma2(ay, W[ii][1], w);
                w = fma2(az, W[ii][2], w);
                w = fma2(aw, W[ii][3], w);
                w = relu2(w);
                float h = sh_x[buf][k][ig * 3 + ii];
                acc = fma2(pack2(h, h), w, acc);
            }
            float s0, s1; unpack2(acc, s0, s1);
#pragma unroll
            for (int off = 4; off; off >>= 1) {
                s0 += __shfl_down_sync(0xffffffffu, s0, off);
                s1 += __shfl_down_sync(0xffffffffu, s1, off);
            }
            if (ig == 0) {
                int dst = sh_dst[buf][k];
                atomicAdd(&d_agg1[dst * H + 2 * cp],     s0);
                atomicAdd(&d_agg1[dst * H + 2 * cp + 1], s1);
            }
        }
        buf ^= 1;
    }
}

// ---------------- BN stats (fp32, float4 loads) ----------------
__global__ void k_stats(int layer) {
    const float4* __restrict__ src = (const float4*)(layer ? d_agg2 : d_agg1);
    int og = threadIdx.x & 15;   // column group of 4
    int r  = threadIdx.x >> 4;   // 16 rows in flight
    float4 s  = make_float4(0.f, 0.f, 0.f, 0.f);
    float4 ss = make_float4(0.f, 0.f, 0.f, 0.f);
#pragma unroll 2
    for (int n = blockIdx.x * 16 + r; n < N_NODES; n += gridDim.x * 16) {
        float4 v = src[n * 16 + og];
        s.x += v.x; s.y += v.y; s.z += v.z; s.w += v.w;
        ss.x += v.x * v.x; ss.y += v.y * v.y; ss.z += v.z * v.z; ss.w += v.w * v.w;
    }
    __shared__ float4 shs[256], shss[256];
    shs[threadIdx.x] = s; shss[threadIdx.x] = ss;
    __syncthreads();
    for (int str = 128; str >= 16; str >>= 1) {
        if (threadIdx.x < str) {
            float4 a = shs[threadIdx.x], b = shs[threadIdx.x + str];
            shs[threadIdx.x] = make_float4(a.x + b.x, a.y + b.y, a.z + b.z, a.w + b.w);
            a = shss[threadIdx.x]; b = shss[threadIdx.x + str];
            shss[threadIdx.x] = make_float4(a.x + b.x, a.y + b.y, a.z + b.z, a.w + b.w);
        }
        __syncthreads();
    }
    if (threadIdx.x < 16) {
        float4 a = shs[threadIdx.x], b = shss[threadIdx.x];
        float* ps = &d_stats[layer * 2 * H + threadIdx.x * 4];
        float* pq = &d_stats[layer * 2 * H + H + threadIdx.x * 4];
        atomicAdd(&ps[0], a.x); atomicAdd(&ps[1], a.y); atomicAdd(&ps[2], a.z); atomicAdd(&ps[3], a.w);
        atomicAdd(&pq[0], b.x); atomicAdd(&pq[1], b.y); atomicAdd(&pq[2], b.z); atomicAdd(&pq[3], b.w);
    }
}

// ---------------- BN finalize (double, 64 threads) ----------------
__global__ void k_finalize(int layer, const float* __restrict__ g,
                           const float* __restrict__ beta) {
    int o = threadIdx.x;
    if (o >= H) return;
    double s  = (double)d_stats[layer * 2 * H + o];
    double ss = (double)d_stats[layer * 2 * H + H + o];
    double mu  = s / (double)N_NODES;
    double var = ss / (double)N_NODES - mu * mu;
    float rs = (float)(1.0 / sqrt(var + BN_EPS));
    float sc = __ldg(&g[o]) * rs;
    d_scale[layer * H + o] = sc;
    d_shift[layer * H + o] = __ldg(&beta[o]) - (float)mu * sc;
}

// ---------------- fused: BN1-apply + ReLU -> h1 ; agg2 = h1 @ root2 + b2 ----------------
// 16 nodes per block of 256 threads
__global__ __launch_bounds__(256, 4)
void k_init_agg2(const float* __restrict__ b2) {
    __shared__ u64   sh_r2[64 * 32];      // 16KB packed root2
    __shared__ float sh_h[16][H];
    const int tid = threadIdx.x;
    const int wid = tid >> 5, lane = tid & 31;
    const int nb = blockIdx.x * 16;

    for (int t = tid; t < 64 * 32; t += 256) sh_r2[t] = d_root2p[t];

    // Phase A: load agg1 rows, apply BN+ReLU, stash to shared + d_h1
    float2 sc = ((const float2*)d_scale)[lane];
    float2 sf = ((const float2*)d_shift)[lane];
#pragma unroll
    for (int rep = 0; rep < 2; rep++) {
        int nl = wid + rep * 8;
        int node = nb + nl;
        float2 v = ((const float2*)&d_agg1[node * H])[lane];
        v.x = fmaxf(fmaf(v.x, sc.x, sf.x), 0.f);
        v.y = fmaxf(fmaf(v.y, sc.y, sf.y), 0.f);
        ((float2*)&sh_h[nl][0])[lane] = v;
        ((float2*)&d_h1[node * H])[lane] = v;
    }
    __syncthreads();

    // Phase B: thread = (node pair, column pair)
    const int cp = tid & 31;
    const int nl0 = (tid >> 5) * 2, nl1 = nl0 + 1;
    u64 bias = pack2(__ldg(&b2[2 * cp]), __ldg(&b2[2 * cp + 1]));
    u64 acc0 = bias, acc1 = bias;
#pragma unroll
    for (int i = 0; i < H; i++) {
        u64 w2 = sh_r2[i * 32 + cp];
        float h0 = sh_h[nl0][i], h1 = sh_h[nl1][i];
        acc0 = fma2(pack2(h0, h0), w2, acc0);
        acc1 = fma2(pack2(h1, h1), w2, acc1);
    }
    float a, b;
    unpack2(acc0, a, b); ((float2*)&d_agg2[(nb + nl0) * H])[cp] = make_float2(a, b);
    unpack2(acc1, a, b); ((float2*)&d_agg2[(nb + nl1) * H])[cp] = make_float2(a, b);
}

// ---------------- layer-2 edge kernel (dominant) ----------------
// thread: cp = tid>>3 (column pair), ig = tid&7 (i-group of 8)
__global__ __launch_bounds__(256, 2)
void k_edge2(const float4* __restrict__ ea4, const int* __restrict__ eidx) {
    const int tid = threadIdx.x;
    const int cp = tid >> 3;
    const int ig = tid & 7;
    const int wid = tid >> 5, lane = tid & 31;
    u64 W[8][4]; u64 B[8];
#pragma unroll
    for (int ii = 0; ii < 8; ii++) {
        int i = ig * 8 + ii;
#pragma unroll
        for (int f = 0; f < 4; f++) W[ii][f] = d_We2p[(i * 32 + cp) * 4 + f];
        B[ii] = d_be2p[i * 32 + cp];
    }
    __shared__ float  sh_h[2][EB][H];
    __shared__ float4 sh_ea[2][EB];
    __shared__ int    sh_dst[2][EB];

    auto load = [&](int b, int buf) {
        int e = b + wid;
        if (e < N_EDGES) {
            int src = __ldg(&eidx[e]);
            float2 v = __ldg((const float2*)&d_h1[src * H] + lane);
            ((float2*)&sh_h[buf][wid][0])[lane] = v;
            if (lane == 0) {
                sh_ea[buf][wid]  = __ldg(&ea4[e]);
                sh_dst[buf][wid] = __ldg(&eidx[N_EDGES + e]);
            }
        }
    };

    const int step = gridDim.x * EB;
    int base = blockIdx.x * EB;
    load(base, 0);
    int buf = 0;
    for (int b = base; b < N_EDGES; b += step) {
        __syncthreads();
        if (b + step < N_EDGES) load(b + step, buf ^ 1);
        int emax = min(EB, N_EDGES - b);
        for (int k = 0; k < emax; k++) {
            float4 a = sh_ea[buf][k];
            u64 ax = pack2(a.x, a.x), ay = pack2(a.y, a.y);
            u64 az = pack2(a.z, a.z), aw = pack2(a.w, a.w);
            u64 acc = 0ULL;
#pragma unroll
            for (int ii = 0; ii < 8; ii++) {
                u64 w = fma2(ax, W[ii][0], B[ii]);
                w = fma2(ay, W[ii][1], w);
                w = fma2(az, W[ii][2], w);
                w = fma2(aw, W[ii][3], w);
                w = relu2(w);
                float h = sh_h[buf][k][ig * 8 + ii];
                acc = fma2(pack2(h, h), w, acc);
            }
            float s0, s1; unpack2(acc, s0, s1);
#pragma unroll
            for (int off = 4; off; off >>= 1) {
                s0 += __shfl_down_sync(0xffffffffu, s0, off);
                s1 += __shfl_down_sync(0xffffffffu, s1, off);
            }
            if (ig == 0) {
                int dst = sh_dst[buf][k];
                atomicAdd(&d_agg2[dst * H + 2 * cp],     s0);
                atomicAdd(&d_agg2[dst * H + 2 * cp + 1], s1);
            }
        }
        buf ^= 1;
    }
}

// ---------------- BN2 apply + ReLU + FC + sigmoid ----------------
__global__ void k_final(const float* __restrict__ Wfc, const float* __restrict__ bfc,
                        float* __restrict__ out) {
    __shared__ float sh_w[8];
    int idx = blockIdx.x * blockDim.x + threadIdx.x;
    int n = idx >> 6, o = idx & 63;
    float p = 0.f;
    if (n < N_NODES) {
        float v = fmaxf(fmaf(d_agg2[idx], d_scale[H + o], d_shift[H + o]), 0.f);
        p = v * __ldg(&Wfc[o]);
    }
#pragma unroll
    for (int off = 16; off > 0; off >>= 1)
        p += __shfl_down_sync(0xffffffffu, p, off);
    if ((threadIdx.x & 31) == 0) sh_w[threadIdx.x >> 5] = p;
    __syncthreads();
    if (threadIdx.x < 4) {
        int nn = blockIdx.x * 4 + threadIdx.x;
        if (nn < N_NODES) {
            float t = sh_w[2 * threadIdx.x] + sh_w[2 * threadIdx.x + 1] + __ldg(bfc);
            out[nn] = 1.f / (1.f + expf(-t));
        }
    }
}

// ---------------- launch ----------------
extern "C" void kernel_launch(void* const* d_in, const int* in_sizes, int n_in,
                              void* d_out, int out_size) {
    const float* x     = (const float*)d_in[0];
    const float* ea    = (const float*)d_in[1];
    const float* We1   = (const float*)d_in[2];
    const float* be1   = (const float*)d_in[3];
    const float* root1 = (const float*)d_in[4];
    const float* b1    = (const float*)d_in[5];
    const float* g1    = (const float*)d_in[6];
    const float* beta1 = (const float*)d_in[7];
    const float* We2   = (const float*)d_in[8];
    const float* be2   = (const float*)d_in[9];
    const float* root2 = (const float*)d_in[10];
    const float* b2    = (const float*)d_in[11];
    const float* g2    = (const float*)d_in[12];
    const float* beta2 = (const float*)d_in[13];
    const float* Wfc   = (const float*)d_in[14];
    const float* bfc   = (const float*)d_in[15];
    const int*   eidx  = (const int*)d_in[16];
    float* out = (float*)d_out;

    const int NB_ELEM = (N_NODES * H + 255) / 256;   // 12500

    k_prep<<<32, 256>>>(We1, be1, We2, be2, root2);
    k_init_agg1<<<NB_ELEM, 256>>>(x, root1, b1);
    k_edge1<<<296, 256>>>(x, (const float4*)ea, eidx);
    k_stats<<<148, 256>>>(0);
    k_finalize<<<1, 64>>>(0, g1, beta1);
    k_init_agg2<<<N_NODES / 16, 256>>>(b2);
    k_edge2<<<296, 256>>>((const float4*)ea, eidx);
    k_stats<<<148, 256>>>(1);
    k_finalize<<<1, 64>>>(1, g2, beta2);
    k_final<<<NB_ELEM, 256>>>(Wfc, bfc, out);
}